// round 13
// baseline (speedup 1.0000x reference)
#include <cuda_runtime.h>
#include <cstdint>

#define Bn 64
#define Sn 128
#define Dn 512
#define Tn 64
#define N3 1536      // 3*D
#define GK 515       // D + 3
#define GKP 528      // padded to multiple of 16

// ---------------- scratch (device globals; no allocation) ----------------
__device__ float g_Uk[Bn * Sn * Dn];        // [B,S,D] keys projection
__device__ float g_h[Bn * Dn];              // hidden state (in-place update)
__device__ float g_qpart[8][Bn * Dn];       // split-K partials of q
__device__ float g_gipart[4][Bn * N3];      // split-K partials of gi
__device__ float g_ghpart[4][Bn * N3];      // split-K partials of gh
__device__ float g_gin[Bn * GKP];           // [ctx | x | zero-pad]
__device__ float g_Wpad[N3 * GKP];          // W_ih zero-padded to K=528

__device__ __forceinline__ float tanh_fast(float x) {
    float y; asm("tanh.approx.f32 %0, %1;" : "=f"(y) : "f"(x)); return y;
}

__device__ __forceinline__ void prefetch_L1(const void* p) {
    asm volatile("prefetch.global.L1 [%0];" :: "l"(p));
}

__device__ __forceinline__ void bsync(int barid) {
    asm volatile("bar.sync %0, %1;" :: "r"(barid), "r"(256) : "memory");
}

// ---- packed fp32x2 math (sm_103a; ptxas never auto-emits FFMA2) ----
__device__ __forceinline__ void fma_f32x2(unsigned long long& d,
                                          unsigned long long a,
                                          unsigned long long b) {
    asm("fma.rn.f32x2 %0, %1, %2, %0;" : "+l"(d) : "l"(a), "l"(b));
}
__device__ __forceinline__ unsigned long long pack2(float x) {
    unsigned long long r;
    asm("mov.b64 %0, {%1, %1};" : "=l"(r) : "f"(x));
    return r;
}
__device__ __forceinline__ float2 unpack2(unsigned long long v) {
    float2 r;
    asm("mov.b64 {%0, %1}, %2;" : "=f"(r.x), "=f"(r.y) : "l"(v));
    return r;
}

__device__ __forceinline__ float gru_one(float gir, float ghr, float giz, float ghz,
                                         float gnn, float ghn, float h) {
    float r = 1.f / (1.f + __expf(-(gir + ghr)));
    float z = 1.f / (1.f + __expf(-(giz + ghz)));
    float n = tanhf(gnn + r * ghn);
    return (1.f - z) * n + z * h;
}

__device__ __forceinline__ void add4(float4& a, const float* p) {
    float4 v = *(const float4*)p;
    a.x += v.x; a.y += v.y; a.z += v.z; a.w += v.w;
}

struct SmemGemm { float As[16][68]; float Bs[16][68]; };   // 8704 B

// C[64 x 64] tile of  C = A(MxK) * B  (+bias), BK=16, 256 threads (tid 0..255),
// packed fma.rn.f32x2 inner product (bitwise-identical IEEE fp32 FMA).
// Synchronization via named barrier `barid` with count 256 — callable by a
// 256-thread subgroup of a larger block.
// NT=false: B row-major [K,N];  NT=true: B row-major [N,K].
template <bool NT>
__device__ __forceinline__ void gemm64b(const float* __restrict__ A, int lda,
                                        const float* __restrict__ B, int ldb,
                                        float* __restrict__ C, int ldc,
                                        const float* __restrict__ bias,
                                        int m0, int n0, int k0, int kiters,
                                        SmemGemm& s, int barid, int tid)
{
    const int tx = tid & 15, ty = tid >> 4;
    const int am = tid >> 2, ak = (tid & 3) << 2;
    unsigned long long acc2[4][2] = {};   // 4 rows x 2 col-pairs, packed f32x2

    for (int it = 0; it < kiters; ++it) {
        const int k = k0 + it * 16;
        float4 a4 = *(const float4*)&A[(size_t)(m0 + am) * lda + k + ak];
        float4 b4;
        if (NT) {
            b4 = *(const float4*)&B[(size_t)(n0 + am) * ldb + k + ak];
        } else {
            const int bk = tid >> 4, bn = (tid & 15) << 2;
            b4 = *(const float4*)&B[(size_t)(k + bk) * ldb + n0 + bn];
        }
        bsync(barid);
        s.As[ak + 0][am] = a4.x; s.As[ak + 1][am] = a4.y;
        s.As[ak + 2][am] = a4.z; s.As[ak + 3][am] = a4.w;
        if (NT) {
            s.Bs[ak + 0][am] = b4.x; s.Bs[ak + 1][am] = b4.y;
            s.Bs[ak + 2][am] = b4.z; s.Bs[ak + 3][am] = b4.w;
        } else {
            const int bk = tid >> 4, bn = (tid & 15) << 2;
            *(float4*)&s.Bs[bk][bn] = b4;
        }
        bsync(barid);
        #pragma unroll
        for (int kk = 0; kk < 16; ++kk) {
            float4 av = *(const float4*)&s.As[kk][ty << 2];
            ulonglong2 bp = *(const ulonglong2*)&s.Bs[kk][tx << 2];
            unsigned long long a0 = pack2(av.x), a1 = pack2(av.y);
            unsigned long long a2 = pack2(av.z), a3 = pack2(av.w);
            fma_f32x2(acc2[0][0], a0, bp.x); fma_f32x2(acc2[0][1], a0, bp.y);
            fma_f32x2(acc2[1][0], a1, bp.x); fma_f32x2(acc2[1][1], a1, bp.y);
            fma_f32x2(acc2[2][0], a2, bp.x); fma_f32x2(acc2[2][1], a2, bp.y);
            fma_f32x2(acc2[3][0], a3, bp.x); fma_f32x2(acc2[3][1], a3, bp.y);
        }
    }

    float4 bi = make_float4(0.f, 0.f, 0.f, 0.f);
    if (bias) bi = *(const float4*)&bias[n0 + (tx << 2)];
    #pragma unroll
    for (int u = 0; u < 4; ++u) {
        float2 c01 = unpack2(acc2[u][0]);
        float2 c23 = unpack2(acc2[u][1]);
        float4 o;
        o.x = c01.x + bi.x; o.y = c01.y + bi.y;
        o.z = c23.x + bi.z; o.w = c23.y + bi.w;
        *(float4*)&C[(size_t)(m0 + (ty << 2) + u) * ldc + n0 + (tx << 2)] = o;
    }
}

// ---------------- kernels ----------------

__global__ void k_init(const float* __restrict__ e_last,
                       const float* __restrict__ W_ih)
{
    const int i = blockIdx.x * blockDim.x + threadIdx.x;
    const int stride = gridDim.x * blockDim.x;
    if (i < Bn * Dn) g_h[i] = e_last[i];
    if (i < Bn * 16) {                     // zero x + pad region of gin
        int b = i >> 4, k = i & 15;
        g_gin[b * GKP + Dn + k] = 0.f;
    }
    for (int j = i; j < N3 * GKP; j += stride) {
        int n = j / GKP, k = j - n * GKP;
        g_Wpad[j] = (k < GK) ? W_ih[n * GK + k] : 0.f;
    }
}

// Uk = e_all @ Ua_w + Ua_b    (M = B*S = 8192, N = K = 512)
__global__ void k_uk(const float* __restrict__ e_all,
                     const float* __restrict__ Ua_w,
                     const float* __restrict__ Ua_b)
{
    __shared__ SmemGemm s;
    gemm64b<false>(e_all, Dn, Ua_w, Dn, g_Uk, Dn, Ua_b,
                   blockIdx.y * 64, blockIdx.x * 64, 0, 32, s, 0, threadIdx.x);
}

// GRU gates: h(in)+parts -> h(out), PLUS out = h_new @ Wo + b.  grid = 32 CTAs.
__global__ void k_gates(const float* __restrict__ b_ih,
                        const float* __restrict__ b_hh,
                        const float* __restrict__ hin,
                        float* __restrict__ hout,
                        const float* __restrict__ Wo_w,
                        const float* __restrict__ Wo_b,
                        float* __restrict__ d_outputs,
                        int tout)
{
    __shared__ float so[8][3];
    const int tid = threadIdx.x;
    const int lane = tid & 31, wid = tid >> 5;
    const int g = (blockIdx.x * 256 + tid) << 2;  // element base (step 4)
    const int b = g >> 9, j = g & 511;
    const int gb = b * N3 + j;

    // ---- static prologue (overlaps predecessor via PDL) ----
    if (tid < 48) prefetch_L1(&Wo_w[tid * 32]);
    float4 gir = make_float4(b_ih[j], b_ih[j + 1], b_ih[j + 2], b_ih[j + 3]);
    float4 giz = make_float4(b_ih[Dn + j], b_ih[Dn + j + 1],
                             b_ih[Dn + j + 2], b_ih[Dn + j + 3]);
    float4 gnn = make_float4(b_ih[2 * Dn + j], b_ih[2 * Dn + j + 1],
                             b_ih[2 * Dn + j + 2], b_ih[2 * Dn + j + 3]);
    float4 ghr = make_float4(b_hh[j], b_hh[j + 1], b_hh[j + 2], b_hh[j + 3]);
    float4 ghz = make_float4(b_hh[Dn + j], b_hh[Dn + j + 1],
                             b_hh[Dn + j + 2], b_hh[Dn + j + 3]);
    float4 ghn = make_float4(b_hh[2 * Dn + j], b_hh[2 * Dn + j + 1],
                             b_hh[2 * Dn + j + 2], b_hh[2 * Dn + j + 3]);

    cudaGridDependencySynchronize();

    #pragma unroll
    for (int p = 0; p < 4; ++p) {
        add4(gir, &g_gipart[p][gb]);
        add4(giz, &g_gipart[p][gb + Dn]);
        add4(gnn, &g_gipart[p][gb + 2 * Dn]);
        add4(ghr, &g_ghpart[p][gb]);
        add4(ghz, &g_ghpart[p][gb + Dn]);
        add4(ghn, &g_ghpart[p][gb + 2 * Dn]);
    }
    float4 h4 = *(const float4*)&hin[g];
    float4 o;
    o.x = gru_one(gir.x, ghr.x, giz.x, ghz.x, gnn.x, ghn.x, h4.x);
    o.y = gru_one(gir.y, ghr.y, giz.y, ghz.y, gnn.y, ghn.y, h4.y);
    o.z = gru_one(gir.z, ghr.z, giz.z, ghz.z, gnn.z, ghn.z, h4.z);
    o.w = gru_one(gir.w, ghr.w, giz.w, ghz.w, gnn.w, ghn.w, h4.w);
    *(float4*)&hout[g] = o;

    // out[b, c] = sum_j h_new[b,j] * Wo[j,c]
    const float* wp = &Wo_w[j * 3];
    float p0 = o.x * wp[0] + o.y * wp[3] + o.z * wp[6] + o.w * wp[9];
    float p1 = o.x * wp[1] + o.y * wp[4] + o.z * wp[7] + o.w * wp[10];
    float p2 = o.x * wp[2] + o.y * wp[5] + o.z * wp[8] + o.w * wp[11];
    #pragma unroll
    for (int off = 16; off > 0; off >>= 1) {
        p0 += __shfl_down_sync(0xffffffffu, p0, off);
        p1 += __shfl_down_sync(0xffffffffu, p1, off);
        p2 += __shfl_down_sync(0xffffffffu, p2, off);
    }
    if (lane == 0) { so[wid][0] = p0; so[wid][1] = p1; so[wid][2] = p2; }
    __syncthreads();
    if ((tid & 127) < 3) {
        const int c = tid & 127;
        const int w0i = (tid >> 7) << 2;
        const int bb = blockIdx.x * 2 + (tid >> 7);
        float acc = so[w0i][c] + so[w0i + 1][c] + so[w0i + 2][c] + so[w0i + 3][c]
                  + Wo_b[c];
        d_outputs[((size_t)bb * Tn + tout) * 3 + c] = acc;
        g_gin[bb * GKP + Dn + c] = acc;
    }
    cudaTriggerProgrammaticLaunchCompletion();
}

// q partials = h @ Wa  (N=512, split-K 8).  grid = 64 CTAs (8 nt x 8 parts).
__global__ void k_q(const float* __restrict__ Wa_w)
{
    __shared__ SmemGemm s;
    const int part = blockIdx.x & 7, nt = blockIdx.x >> 3;
    const int tid = threadIdx.x;

    if (tid < 128) {
        const int r = tid >> 1, c = (tid & 1) << 5;
        prefetch_L1(&Wa_w[(size_t)(part * 64 + r) * Dn + nt * 64 + c]);
    }
    cudaGridDependencySynchronize();

    gemm64b<false>(g_h, Dn, Wa_w, Dn, g_qpart[part], Dn, nullptr,
                   0, nt * 64, part * 64, 4, s, 0, tid);
    cudaTriggerProgrammaticLaunchCompletion();
}

// Attention smem layout (21016 B), unioned with 4x SmemGemm (34816 B)
struct AttnSmem {
    float cpart[8][Dn];
    float qs[Dn];
    float vas[Dn];
    float ws[Sn];
    float red[4];
    float smax, sinv;
};

// Heterogeneous grid (88 CTAs x 1024 threads):
//   CTAs 0..63  : fused per-batch attention (scores -> softmax -> ctx),
//                 griddepsync on k_q's trigger.
//   CTAs 64..87 : gh partials = h @ W_hh^T, NO griddepsync — g_h is final
//                 before this grid can launch (launch follows q's end-trigger,
//                 which follows gates' end-trigger).  Each CTA runs 4
//                 independent 64x64 GEMM tiles on 256-thread subgroups with
//                 named barriers — overlaps attention on otherwise-idle SMs.
// k_gi syncs on THIS grid's completion trigger, so the next k_gates is
// transitively ordered after gh as well.  No races.
__global__ void __launch_bounds__(1024, 1)
k_attn_gh(const float* __restrict__ e_all,
          const float* __restrict__ Wa_b,
          const float* __restrict__ Va_w,
          const float* __restrict__ Va_b,
          const float* __restrict__ W_hh,
          float* __restrict__ cross, int t)
{
    __shared__ __align__(16) char smraw[4 * sizeof(SmemGemm)];  // 34816 B
    const int tid = threadIdx.x;
    const int cta = blockIdx.x;

    if (cta >= 64) {
        // ---------------- gh half ----------------
        const int sub = tid >> 8;          // subgroup 0..3
        const int stid = tid & 255;
        const int tile = (cta - 64) * 4 + sub;   // 0..95
        const int part = tile & 3, nt = tile >> 2;
        SmemGemm& g = reinterpret_cast<SmemGemm*>(smraw)[sub];
        // prefetch this tile's W_hh slice
        {
            const int r = stid >> 2, o = stid & 3;
            prefetch_L1(&W_hh[(size_t)(nt * 64 + r) * Dn + part * 128 + o * 32]);
        }
        gemm64b<true>(g_h, Dn, W_hh, Dn, g_ghpart[part], N3, nullptr,
                      0, nt * 64, part * 128, 8, g, sub + 1, stid);
        cudaTriggerProgrammaticLaunchCompletion();
        return;
    }

    // ---------------- attention half ----------------
    AttnSmem& a = *reinterpret_cast<AttnSmem*>(smraw);
    const int lane = tid & 31, wid = tid >> 5;
    const int b = cta;
    const float* ukb = g_Uk + (size_t)b * Sn * Dn;

    // prologue: warm L1 with this batch's Uk slice (guard t>0: k_uk may be in flight)
    if (t > 0) {
        prefetch_L1(ukb + (size_t)tid * 32);
        prefetch_L1(ukb + (size_t)(tid + 1024) * 32);
    }
    float qb = 0.f, vaw = 0.f;
    if (tid < Dn) { qb = Wa_b[tid]; vaw = Va_w[tid]; }
    const float vb0 = Va_b[0];

    cudaGridDependencySynchronize();

    // q = sum of 8 parts + bias (512 threads), Va -> smem
    if (tid < Dn) {
        float q = qb;
        #pragma unroll
        for (int p = 0; p < 8; ++p) q += g_qpart[p][b * Dn + tid];
        a.qs[tid] = q;
        a.vas[tid] = vaw;
    }
    __syncthreads();

    // scores: 32 warps x 4 rows
    #pragma unroll
    for (int r = 0; r < 4; ++r) {
        const int s = (wid << 2) + r;
        const float4* uk4 = (const float4*)(ukb + (size_t)s * Dn);
        float sum = 0.f;
        #pragma unroll
        for (int i = 0; i < 4; ++i) {
            const int v = lane + (i << 5);
            float4 u = uk4[v];
            float4 q4 = *(const float4*)&a.qs[v << 2];
            float4 a4 = *(const float4*)&a.vas[v << 2];
            sum += tanh_fast(q4.x + u.x) * a4.x;
            sum += tanh_fast(q4.y + u.y) * a4.y;
            sum += tanh_fast(q4.z + u.z) * a4.z;
            sum += tanh_fast(q4.w + u.w) * a4.w;
        }
        #pragma unroll
        for (int o = 16; o > 0; o >>= 1)
            sum += __shfl_down_sync(0xffffffffu, sum, o);
        if (lane == 0) a.ws[s] = sum + vb0;
    }
    __syncthreads();

    // softmax over S=128 (first 4 warps)
    float sc = (tid < Sn) ? a.ws[tid] : -3.4e38f;
    if (tid < Sn) {
        float v = sc;
        #pragma unroll
        for (int o = 16; o > 0; o >>= 1)
            v = fmaxf(v, __shfl_xor_sync(0xffffffffu, v, o));
        if (lane == 0) a.red[wid] = v;
    }
    __syncthreads();
    if (tid == 0)
        a.smax = fmaxf(fmaxf(a.red[0], a.red[1]), fmaxf(a.red[2], a.red[3]));
    __syncthreads();
    float e = 0.f;
    if (tid < Sn) {
        e = __expf(sc - a.smax);
        float es = e;
        #pragma unroll
        for (int o = 16; o > 0; o >>= 1)
            es += __shfl_xor_sync(0xffffffffu, es, o);
        if (lane == 0) a.red[wid] = es;
    }
    __syncthreads();
    if (tid == 0)
        a.sinv = 1.f / (a.red[0] + a.red[1] + a.red[2] + a.red[3]);
    __syncthreads();
    if (tid < Sn) {
        float w = e * a.sinv;
        a.ws[tid] = w;
        cross[((size_t)b * Tn + t) * Sn + tid] = w;
    }
    __syncthreads();

    // ctx: thread handles float4 of d (128 groups), 8 s-groups of 16
    {
        const int d4 = (tid & 127) << 2;
        const int sg = tid >> 7;
        const float4* eb = (const float4*)(e_all + (size_t)b * Sn * Dn + d4);
        float4 acc = make_float4(0.f, 0.f, 0.f, 0.f);
        #pragma unroll
        for (int s = sg << 4; s < (sg << 4) + 16; ++s) {
            float4 v = eb[(size_t)s * (Dn / 4)];
            float w = a.ws[s];
            acc.x += w * v.x; acc.y += w * v.y;
            acc.z += w * v.z; acc.w += w * v.w;
        }
        *(float4*)&a.cpart[sg][d4] = acc;
    }
    __syncthreads();
    if (tid < Dn) {
        float acc = 0.f;
        #pragma unroll
        for (int sg = 0; sg < 8; ++sg) acc += a.cpart[sg][tid];
        g_gin[b * GKP + tid] = acc;
    }
    cudaTriggerProgrammaticLaunchCompletion();
}

// gi partials = gin @ Wpad^T   (N=1536, K=528, split-K 4).  grid = 96.
__global__ void k_gi()
{
    __shared__ SmemGemm s;
    const int part = blockIdx.x & 3;
    const int nt = blockIdx.x >> 2;
    const int k0 = (part < 3) ? part * 128 : 384;
    const int ki = (part < 3) ? 8 : 9;
    const int tid = threadIdx.x;
    for (int i = tid; i < 320; i += 256) {
        const int r = i / 5, o = i - r * 5;
        prefetch_L1(&g_Wpad[(size_t)(nt * 64 + r) * GKP + k0 + o * 32]);
    }
    cudaGridDependencySynchronize();
    gemm64b<true>(g_gin, GKP, g_Wpad, GKP, g_gipart[part], N3, nullptr,
                  0, nt * 64, k0, ki, s, 0, tid);
    cudaTriggerProgrammaticLaunchCompletion();
}

// ---------------- launch helpers ----------------
template <typename F, typename... Args>
static inline void pdl_launch(F* kern, dim3 grid, dim3 block, Args... args)
{
    cudaLaunchConfig_t cfg = {};
    cfg.gridDim = grid;
    cfg.blockDim = block;
    cfg.dynamicSmemBytes = 0;
    cfg.stream = 0;
    cudaLaunchAttribute attr = {};
    attr.id = cudaLaunchAttributeProgrammaticStreamSerialization;
    attr.val.programmaticStreamSerializationAllowed = 1;
    cfg.attrs = &attr;
    cfg.numAttrs = 1;
    cudaLaunchKernelEx(&cfg, kern, args...);
}

// ---------------- launch ----------------
extern "C" void kernel_launch(void* const* d_in, const int* in_sizes, int n_in,
                              void* d_out, int out_size)
{
    const float* e_all  = (const float*)d_in[0];
    const float* e_last = (const float*)d_in[1];
    const float* Wa_w   = (const float*)d_in[2];
    const float* Wa_b   = (const float*)d_in[3];
    const float* Ua_w   = (const float*)d_in[4];
    const float* Ua_b   = (const float*)d_in[5];
    const float* Va_w   = (const float*)d_in[6];
    const float* Va_b   = (const float*)d_in[7];
    const float* W_ih   = (const float*)d_in[8];
    const float* W_hh   = (const float*)d_in[9];
    const float* b_ih   = (const float*)d_in[10];
    const float* b_hh   = (const float*)d_in[11];
    const float* Wo_w   = (const float*)d_in[12];
    const float* Wo_b   = (const float*)d_in[13];

    float* out       = (float*)d_out;
    float* d_outputs = out;                        // [B,T,3]
    float* hT        = out + Bn * Tn * 3;          // [1,B,D]
    float* cross     = hT + Bn * Dn;               // [B,T,S]

    float* g_h_ptr = nullptr;
    cudaGetSymbolAddress((void**)&g_h_ptr, g_h);

    k_init<<<512, 256>>>(e_last, W_ih);
    k_uk<<<dim3(Dn / 64, (Bn * Sn) / 64), 256>>>(e_all, Ua_w, Ua_b);

    for (int t = 0; t < Tn; ++t) {
        if (t > 0)
            pdl_launch(k_gates, dim3(32), dim3(256),
                       b_ih, b_hh, (const float*)g_h_ptr, g_h_ptr,
                       Wo_w, Wo_b, d_outputs, t - 1);
        pdl_launch(k_q, dim3(64), dim3(256), Wa_w);
        pdl_launch(k_attn_gh, dim3(64 + 24), dim3(1024),
                   e_all, Wa_b, Va_w, Va_b, W_hh, cross, t);
        pdl_launch(k_gi, dim3(96), dim3(256));
    }
    pdl_launch(k_gates, dim3(32), dim3(256),
               b_ih, b_hh, (const float*)g_h_ptr, hT,
               Wo_w, Wo_b, d_outputs, Tn - 1);
}

// round 14
// speedup vs baseline: 1.3682x; 1.3682x over previous
#include <cuda_runtime.h>
#include <cstdint>

#define Bn 64
#define Sn 128
#define Dn 512
#define Tn 64
#define N3 1536      // 3*D
#define GK 515       // D + 3
#define GKP 528      // padded to multiple of 16

// ---------------- scratch (device globals; no allocation) ----------------
__device__ float g_Uk[Bn * Sn * Dn];        // [B,S,D] keys projection
__device__ float g_h[Bn * Dn];              // hidden state (in-place update)
__device__ float g_qpart[8][Bn * Dn];       // split-K partials of q
__device__ float g_gipart[4][Bn * N3];      // split-K partials of gi
__device__ float g_ghpart[4][Bn * N3];      // split-K partials of gh
__device__ float g_gin[Bn * GKP];           // [ctx | x | zero-pad]
__device__ float g_Wpad[N3 * GKP];          // W_ih zero-padded to K=528

__device__ __forceinline__ float tanh_fast(float x) {
    float y; asm("tanh.approx.f32 %0, %1;" : "=f"(y) : "f"(x)); return y;
}

__device__ __forceinline__ void prefetch_L1(const void* p) {
    asm volatile("prefetch.global.L1 [%0];" :: "l"(p));
}

// ---- packed fp32x2 math (sm_103a; ptxas never auto-emits FFMA2) ----
__device__ __forceinline__ void fma_f32x2(unsigned long long& d,
                                          unsigned long long a,
                                          unsigned long long b) {
    asm("fma.rn.f32x2 %0, %1, %2, %0;" : "+l"(d) : "l"(a), "l"(b));
}
__device__ __forceinline__ unsigned long long pack2(float x) {
    unsigned long long r;
    asm("mov.b64 %0, {%1, %1};" : "=l"(r) : "f"(x));
    return r;
}
__device__ __forceinline__ float2 unpack2(unsigned long long v) {
    float2 r;
    asm("mov.b64 {%0, %1}, %2;" : "=f"(r.x), "=f"(r.y) : "l"(v));
    return r;
}

__device__ __forceinline__ float gru_one(float gir, float ghr, float giz, float ghz,
                                         float gnn, float ghn, float h) {
    float r = 1.f / (1.f + __expf(-(gir + ghr)));
    float z = 1.f / (1.f + __expf(-(giz + ghz)));
    float n = tanhf(gnn + r * ghn);
    return (1.f - z) * n + z * h;
}

__device__ __forceinline__ void add4(float4& a, const float* p) {
    float4 v = *(const float4*)p;
    a.x += v.x; a.y += v.y; a.z += v.z; a.w += v.w;
}

__device__ __forceinline__ float dot_tanh4(float4 q4, float4 u, float4 a4) {
    return tanh_fast(q4.x + u.x) * a4.x + tanh_fast(q4.y + u.y) * a4.y
         + tanh_fast(q4.z + u.z) * a4.z + tanh_fast(q4.w + u.w) * a4.w;
}

struct SmemGemm { float As[16][68]; float Bs[16][68]; };

// C[64 x 64] tile of  C = A(MxK) * B  (+bias), BK=16, 256 threads, 4x4 microtile.
// Inner product uses packed fma.rn.f32x2 (2 IEEE fp32 FMA per FMA-pipe slot;
// bitwise identical to scalar FFMA).
// NT=false: B row-major [K,N];  NT=true: B row-major [N,K].
template <bool NT>
__device__ __forceinline__ void gemm64(const float* __restrict__ A, int lda,
                                       const float* __restrict__ B, int ldb,
                                       float* __restrict__ C, int ldc,
                                       const float* __restrict__ bias,
                                       int m0, int n0, int k0, int kiters,
                                       SmemGemm& s)
{
    const int tid = threadIdx.x;
    const int tx = tid & 15, ty = tid >> 4;
    const int am = tid >> 2, ak = (tid & 3) << 2;
    unsigned long long acc2[4][2] = {};   // 4 rows x 2 col-pairs, packed f32x2

    for (int it = 0; it < kiters; ++it) {
        const int k = k0 + it * 16;
        float4 a4 = *(const float4*)&A[(size_t)(m0 + am) * lda + k + ak];
        float4 b4;
        if (NT) {
            b4 = *(const float4*)&B[(size_t)(n0 + am) * ldb + k + ak];
        } else {
            const int bk = tid >> 4, bn = (tid & 15) << 2;
            b4 = *(const float4*)&B[(size_t)(k + bk) * ldb + n0 + bn];
        }
        __syncthreads();
        s.As[ak + 0][am] = a4.x; s.As[ak + 1][am] = a4.y;
        s.As[ak + 2][am] = a4.z; s.As[ak + 3][am] = a4.w;
        if (NT) {
            s.Bs[ak + 0][am] = b4.x; s.Bs[ak + 1][am] = b4.y;
            s.Bs[ak + 2][am] = b4.z; s.Bs[ak + 3][am] = b4.w;
        } else {
            const int bk = tid >> 4, bn = (tid & 15) << 2;
            *(float4*)&s.Bs[bk][bn] = b4;
        }
        __syncthreads();
        #pragma unroll
        for (int kk = 0; kk < 16; ++kk) {
            float4 av = *(const float4*)&s.As[kk][ty << 2];
            // Bs row stride = 68 floats = 272B (16B multiple) -> 16B aligned
            ulonglong2 bp = *(const ulonglong2*)&s.Bs[kk][tx << 2];
            unsigned long long a0 = pack2(av.x), a1 = pack2(av.y);
            unsigned long long a2 = pack2(av.z), a3 = pack2(av.w);
            fma_f32x2(acc2[0][0], a0, bp.x); fma_f32x2(acc2[0][1], a0, bp.y);
            fma_f32x2(acc2[1][0], a1, bp.x); fma_f32x2(acc2[1][1], a1, bp.y);
            fma_f32x2(acc2[2][0], a2, bp.x); fma_f32x2(acc2[2][1], a2, bp.y);
            fma_f32x2(acc2[3][0], a3, bp.x); fma_f32x2(acc2[3][1], a3, bp.y);
        }
    }

    float4 bi = make_float4(0.f, 0.f, 0.f, 0.f);
    if (bias) bi = *(const float4*)&bias[n0 + (tx << 2)];
    #pragma unroll
    for (int u = 0; u < 4; ++u) {
        float2 c01 = unpack2(acc2[u][0]);
        float2 c23 = unpack2(acc2[u][1]);
        float4 o;
        o.x = c01.x + bi.x; o.y = c01.y + bi.y;
        o.z = c23.x + bi.z; o.w = c23.y + bi.w;
        *(float4*)&C[(size_t)(m0 + (ty << 2) + u) * ldc + n0 + (tx << 2)] = o;
    }
}

// ---------------- kernels ----------------

__global__ void k_init(const float* __restrict__ e_last,
                       const float* __restrict__ W_ih)
{
    const int i = blockIdx.x * blockDim.x + threadIdx.x;
    const int stride = gridDim.x * blockDim.x;
    if (i < Bn * Dn) g_h[i] = e_last[i];
    if (i < Bn * 16) {                     // zero x + pad region of gin
        int b = i >> 4, k = i & 15;
        g_gin[b * GKP + Dn + k] = 0.f;
    }
    for (int j = i; j < N3 * GKP; j += stride) {
        int n = j / GKP, k = j - n * GKP;
        g_Wpad[j] = (k < GK) ? W_ih[n * GK + k] : 0.f;
    }
}

// Uk = e_all @ Ua_w + Ua_b    (M = B*S = 8192, N = K = 512)
__global__ void k_uk(const float* __restrict__ e_all,
                     const float* __restrict__ Ua_w,
                     const float* __restrict__ Ua_b)
{
    __shared__ SmemGemm s;
    gemm64<false>(e_all, Dn, Ua_w, Dn, g_Uk, Dn, Ua_b,
                  blockIdx.y * 64, blockIdx.x * 64, 0, 32, s);
}

// GRU gates: h(in)+parts -> h(out), PLUS out = h_new @ Wo + b.  grid = 32 CTAs.
__global__ void k_gates(const float* __restrict__ b_ih,
                        const float* __restrict__ b_hh,
                        const float* __restrict__ hin,
                        float* __restrict__ hout,
                        const float* __restrict__ Wo_w,
                        const float* __restrict__ Wo_b,
                        float* __restrict__ d_outputs,
                        int tout)
{
    __shared__ float so[8][3];
    const int tid = threadIdx.x;
    const int lane = tid & 31, wid = tid >> 5;
    const int g = (blockIdx.x * 256 + tid) << 2;  // element base (step 4)
    const int b = g >> 9, j = g & 511;
    const int gb = b * N3 + j;

    // ---- static prologue (overlaps predecessor via PDL) ----
    if (tid < 48) prefetch_L1(&Wo_w[tid * 32]);
    float4 gir = make_float4(b_ih[j], b_ih[j + 1], b_ih[j + 2], b_ih[j + 3]);
    float4 giz = make_float4(b_ih[Dn + j], b_ih[Dn + j + 1],
                             b_ih[Dn + j + 2], b_ih[Dn + j + 3]);
    float4 gnn = make_float4(b_ih[2 * Dn + j], b_ih[2 * Dn + j + 1],
                             b_ih[2 * Dn + j + 2], b_ih[2 * Dn + j + 3]);
    float4 ghr = make_float4(b_hh[j], b_hh[j + 1], b_hh[j + 2], b_hh[j + 3]);
    float4 ghz = make_float4(b_hh[Dn + j], b_hh[Dn + j + 1],
                             b_hh[Dn + j + 2], b_hh[Dn + j + 3]);
    float4 ghn = make_float4(b_hh[2 * Dn + j], b_hh[2 * Dn + j + 1],
                             b_hh[2 * Dn + j + 2], b_hh[2 * Dn + j + 3]);

    cudaGridDependencySynchronize();

    #pragma unroll
    for (int p = 0; p < 4; ++p) {
        add4(gir, &g_gipart[p][gb]);
        add4(giz, &g_gipart[p][gb + Dn]);
        add4(gnn, &g_gipart[p][gb + 2 * Dn]);
        add4(ghr, &g_ghpart[p][gb]);
        add4(ghz, &g_ghpart[p][gb + Dn]);
        add4(ghn, &g_ghpart[p][gb + 2 * Dn]);
    }
    float4 h4 = *(const float4*)&hin[g];
    float4 o;
    o.x = gru_one(gir.x, ghr.x, giz.x, ghz.x, gnn.x, ghn.x, h4.x);
    o.y = gru_one(gir.y, ghr.y, giz.y, ghz.y, gnn.y, ghn.y, h4.y);
    o.z = gru_one(gir.z, ghr.z, giz.z, ghz.z, gnn.z, ghn.z, h4.z);
    o.w = gru_one(gir.w, ghr.w, giz.w, ghz.w, gnn.w, ghn.w, h4.w);
    *(float4*)&hout[g] = o;

    // out[b, c] = sum_j h_new[b,j] * Wo[j,c]
    const float* wp = &Wo_w[j * 3];
    float p0 = o.x * wp[0] + o.y * wp[3] + o.z * wp[6] + o.w * wp[9];
    float p1 = o.x * wp[1] + o.y * wp[4] + o.z * wp[7] + o.w * wp[10];
    float p2 = o.x * wp[2] + o.y * wp[5] + o.z * wp[8] + o.w * wp[11];
    #pragma unroll
    for (int off = 16; off > 0; off >>= 1) {
        p0 += __shfl_down_sync(0xffffffffu, p0, off);
        p1 += __shfl_down_sync(0xffffffffu, p1, off);
        p2 += __shfl_down_sync(0xffffffffu, p2, off);
    }
    if (lane == 0) { so[wid][0] = p0; so[wid][1] = p1; so[wid][2] = p2; }
    __syncthreads();
    if ((tid & 127) < 3) {
        const int c = tid & 127;
        const int w0i = (tid >> 7) << 2;
        const int bb = blockIdx.x * 2 + (tid >> 7);
        float acc = so[w0i][c] + so[w0i + 1][c] + so[w0i + 2][c] + so[w0i + 3][c]
                  + Wo_b[c];
        d_outputs[((size_t)bb * Tn + tout) * 3 + c] = acc;
        g_gin[bb * GKP + Dn + c] = acc;
    }
    cudaTriggerProgrammaticLaunchCompletion();
}

// q partials = h @ Wa  (N=512, split-K 8).  grid = 64 CTAs (8 nt x 8 parts).
__global__ void k_q(const float* __restrict__ Wa_w)
{
    __shared__ SmemGemm s;
    const int part = blockIdx.x & 7, nt = blockIdx.x >> 3;
    const int tid = threadIdx.x;

    if (tid < 128) {
        const int r = tid >> 1, c = (tid & 1) << 5;
        prefetch_L1(&Wa_w[(size_t)(part * 64 + r) * Dn + nt * 64 + c]);
    }
    cudaGridDependencySynchronize();

    gemm64<false>(g_h, Dn, Wa_w, Dn, g_qpart[part], Dn, nullptr,
                  0, nt * 64, part * 64, 4, s);
    cudaTriggerProgrammaticLaunchCompletion();
}

// fused per-batch attention: one 1024-thread CTA per batch. scores -> softmax
// -> ctx, all CTA-local (__syncthreads only).  grid = 64.  (r10 internals —
// the fastest measured attention.)
__global__ void __launch_bounds__(1024, 1)
k_attn(const float* __restrict__ e_all,
       const float* __restrict__ Wa_b,
       const float* __restrict__ Va_w,
       const float* __restrict__ Va_b,
       float* __restrict__ cross, int t)
{
    __shared__ __align__(16) float cpart[8][Dn];   // 16KB, float4-accessed
    __shared__ __align__(16) float qs[Dn];
    __shared__ __align__(16) float vas[Dn];
    __shared__ __align__(16) float ws[Sn];
    __shared__ float red[4];
    __shared__ float smax, sinv;

    const int tid = threadIdx.x;
    const int lane = tid & 31, wid = tid >> 5;
    const int b = blockIdx.x;
    const float* ukb = g_Uk + (size_t)b * Sn * Dn;

    // prologue: warm L1 with this batch's Uk slice (guard t>0: k_uk may be in flight)
    if (t > 0) {
        prefetch_L1(ukb + (size_t)tid * 32);
        prefetch_L1(ukb + (size_t)(tid + 1024) * 32);
    }
    float qb = 0.f, vaw = 0.f;
    if (tid < Dn) { qb = Wa_b[tid]; vaw = Va_w[tid]; }
    const float vb0 = Va_b[0];

    cudaGridDependencySynchronize();

    // q = sum of 8 parts + bias (512 threads), Va -> smem
    if (tid < Dn) {
        float q = qb;
        #pragma unroll
        for (int p = 0; p < 8; ++p) q += g_qpart[p][b * Dn + tid];
        qs[tid] = q;
        vas[tid] = vaw;
    }
    __syncthreads();

    // scores: 32 warps x 4 rows
    #pragma unroll
    for (int r = 0; r < 4; ++r) {
        const int s = (wid << 2) + r;
        const float4* uk4 = (const float4*)(ukb + (size_t)s * Dn);
        float sum = 0.f;
        #pragma unroll
        for (int i = 0; i < 4; ++i) {
            const int v = lane + (i << 5);
            float4 u = uk4[v];
            float4 q4 = *(const float4*)&qs[v << 2];
            float4 a4 = *(const float4*)&vas[v << 2];
            sum += dot_tanh4(q4, u, a4);
        }
        #pragma unroll
        for (int o = 16; o > 0; o >>= 1)
            sum += __shfl_down_sync(0xffffffffu, sum, o);
        if (lane == 0) ws[s] = sum + vb0;
    }
    __syncthreads();

    // softmax over S=128 (first 4 warps)
    float sc = (tid < Sn) ? ws[tid] : -3.4e38f;
    if (tid < Sn) {
        float v = sc;
        #pragma unroll
        for (int o = 16; o > 0; o >>= 1)
            v = fmaxf(v, __shfl_xor_sync(0xffffffffu, v, o));
        if (lane == 0) red[wid] = v;
    }
    __syncthreads();
    if (tid == 0)
        smax = fmaxf(fmaxf(red[0], red[1]), fmaxf(red[2], red[3]));
    __syncthreads();
    float e = 0.f;
    if (tid < Sn) {
        e = __expf(sc - smax);
        float es = e;
        #pragma unroll
        for (int o = 16; o > 0; o >>= 1)
            es += __shfl_xor_sync(0xffffffffu, es, o);
        if (lane == 0) red[wid] = es;
    }
    __syncthreads();
    if (tid == 0)
        sinv = 1.f / (red[0] + red[1] + red[2] + red[3]);
    __syncthreads();
    if (tid < Sn) {
        float w = e * sinv;
        ws[tid] = w;
        cross[((size_t)b * Tn + t) * Sn + tid] = w;
    }
    __syncthreads();

    // ctx: thread handles float4 of d (128 groups), 8 s-groups of 16
    {
        const int d4 = (tid & 127) << 2;
        const int sg = tid >> 7;
        const float4* eb = (const float4*)(e_all + (size_t)b * Sn * Dn + d4);
        float4 a = make_float4(0.f, 0.f, 0.f, 0.f);
        #pragma unroll
        for (int s = sg << 4; s < (sg << 4) + 16; ++s) {
            float4 v = eb[(size_t)s * (Dn / 4)];
            float w = ws[s];
            a.x += w * v.x; a.y += w * v.y; a.z += w * v.z; a.w += w * v.w;
        }
        *(float4*)&cpart[sg][d4] = a;
    }
    __syncthreads();
    if (tid < Dn) {
        float a = 0.f;
        #pragma unroll
        for (int sg = 0; sg < 8; ++sg) a += cpart[sg][tid];
        g_gin[b * GKP + tid] = a;
    }
    cudaTriggerProgrammaticLaunchCompletion();
}

// gi partials (96 CTAs) + gh partials (96 CTAs) in one launch
__global__ void k_gigh(const float* __restrict__ W_hh)
{
    __shared__ SmemGemm s;
    const int bx = blockIdx.x;
    const int tid = threadIdx.x;
    if (bx < 96) {
        const int part = bx & 3, nt = bx >> 2;
        const int k0 = (part < 3) ? part * 128 : 384;
        const int ki = (part < 3) ? 8 : 9;
        for (int i = tid; i < 320; i += 256) {
            const int r = i / 5, o = i - r * 5;
            prefetch_L1(&g_Wpad[(size_t)(nt * 64 + r) * GKP + k0 + o * 32]);
        }
        cudaGridDependencySynchronize();
        gemm64<true>(g_gin, GKP, g_Wpad, GKP, g_gipart[part], N3, nullptr,
                     0, nt * 64, k0, ki, s);
    } else {
        const int i = bx - 96;
        const int part = i & 3, nt = i >> 2;
        {
            const int r = tid >> 2, o = tid & 3;
            prefetch_L1(&W_hh[(size_t)(nt * 64 + r) * Dn + part * 128 + o * 32]);
        }
        cudaGridDependencySynchronize();
        gemm64<true>(g_h, Dn, W_hh, Dn, g_ghpart[part], N3, nullptr,
                     0, nt * 64, part * 128, 8, s);
    }
    cudaTriggerProgrammaticLaunchCompletion();
}

// ---------------- launch helpers ----------------
template <typename F, typename... Args>
static inline void pdl_launch(F* kern, dim3 grid, dim3 block, Args... args)
{
    cudaLaunchConfig_t cfg = {};
    cfg.gridDim = grid;
    cfg.blockDim = block;
    cfg.dynamicSmemBytes = 0;
    cfg.stream = 0;
    cudaLaunchAttribute attr = {};
    attr.id = cudaLaunchAttributeProgrammaticStreamSerialization;
    attr.val.programmaticStreamSerializationAllowed = 1;
    cfg.attrs = &attr;
    cfg.numAttrs = 1;
    cudaLaunchKernelEx(&cfg, kern, args...);
}

// ---------------- launch ----------------
extern "C" void kernel_launch(void* const* d_in, const int* in_sizes, int n_in,
                              void* d_out, int out_size)
{
    const float* e_all  = (const float*)d_in[0];
    const float* e_last = (const float*)d_in[1];
    const float* Wa_w   = (const float*)d_in[2];
    const float* Wa_b   = (const float*)d_in[3];
    const float* Ua_w   = (const float*)d_in[4];
    const float* Ua_b   = (const float*)d_in[5];
    const float* Va_w   = (const float*)d_in[6];
    const float* Va_b   = (const float*)d_in[7];
    const float* W_ih   = (const float*)d_in[8];
    const float* W_hh   = (const float*)d_in[9];
    const float* b_ih   = (const float*)d_in[10];
    const float* b_hh   = (const float*)d_in[11];
    const float* Wo_w   = (const float*)d_in[12];
    const float* Wo_b   = (const float*)d_in[13];

    float* out       = (float*)d_out;
    float* d_outputs = out;                        // [B,T,3]
    float* hT        = out + Bn * Tn * 3;          // [1,B,D]
    float* cross     = hT + Bn * Dn;               // [B,T,S]

    float* g_h_ptr = nullptr;
    cudaGetSymbolAddress((void**)&g_h_ptr, g_h);

    k_init<<<512, 256>>>(e_last, W_ih);
    k_uk<<<dim3(Dn / 64, (Bn * Sn) / 64), 256>>>(e_all, Ua_w, Ua_b);

    for (int t = 0; t < Tn; ++t) {
        if (t > 0)
            pdl_launch(k_gates, dim3(32), dim3(256),
                       b_ih, b_hh, (const float*)g_h_ptr, g_h_ptr,
                       Wo_w, Wo_b, d_outputs, t - 1);
        pdl_launch(k_q, dim3(64), dim3(256), Wa_w);
        pdl_launch(k_attn, dim3(Bn), dim3(1024),
                   e_all, Wa_b, Va_w, Va_b, cross, t);
        pdl_launch(k_gigh, dim3(192), dim3(256), W_hh);
    }
    pdl_launch(k_gates, dim3(32), dim3(256),
               b_ih, b_hh, (const float*)g_h_ptr, hT,
               Wo_w, Wo_b, d_outputs, Tn - 1);
}

// round 16
// speedup vs baseline: 1.3763x; 1.0059x over previous
#include <cuda_runtime.h>
#include <cstdint>

#define Bn 64
#define Sn 128
#define Dn 512
#define Tn 64
#define N3 1536      // 3*D
#define GK 515       // D + 3
#define GKP 528      // padded to multiple of 16

// ---------------- scratch (device globals; no allocation) ----------------
__device__ float g_Uk[Bn * Sn * Dn];        // [B,S,D] keys projection
__device__ float g_h[Bn * Dn];              // hidden state (in-place update)
__device__ float g_qpart[8][Bn * Dn];       // split-K partials of q
__device__ float g_gipart[4][Bn * N3];      // split-K partials of gi
__device__ float g_ghpart[4][Bn * N3];      // split-K partials of gh
__device__ float g_gin[Bn * GKP];           // [ctx | x | zero-pad]
__device__ float g_Wpad[N3 * GKP];          // W_ih zero-padded to K=528

__device__ __forceinline__ float tanh_fast(float x) {
    float y; asm("tanh.approx.f32 %0, %1;" : "=f"(y) : "f"(x)); return y;
}

__device__ __forceinline__ void prefetch_L1(const void* p) {
    asm volatile("prefetch.global.L1 [%0];" :: "l"(p));
}

// ---- packed fp32x2 math (sm_103a; ptxas never auto-emits FFMA2) ----
__device__ __forceinline__ void fma_f32x2(unsigned long long& d,
                                          unsigned long long a,
                                          unsigned long long b) {
    asm("fma.rn.f32x2 %0, %1, %2, %0;" : "+l"(d) : "l"(a), "l"(b));
}
__device__ __forceinline__ unsigned long long pack2(float x) {
    unsigned long long r;
    asm("mov.b64 %0, {%1, %1};" : "=l"(r) : "f"(x));
    return r;
}
__device__ __forceinline__ float2 unpack2(unsigned long long v) {
    float2 r;
    asm("mov.b64 {%0, %1}, %2;" : "=f"(r.x), "=f"(r.y) : "l"(v));
    return r;
}

__device__ __forceinline__ float gru_one(float gir, float ghr, float giz, float ghz,
                                         float gnn, float ghn, float h) {
    float r = 1.f / (1.f + __expf(-(gir + ghr)));
    float z = 1.f / (1.f + __expf(-(giz + ghz)));
    float n = tanhf(gnn + r * ghn);
    return (1.f - z) * n + z * h;
}

__device__ __forceinline__ void add4(float4& a, const float* p) {
    float4 v = *(const float4*)p;
    a.x += v.x; a.y += v.y; a.z += v.z; a.w += v.w;
}

__device__ __forceinline__ float dot_tanh4(float4 q4, float4 u, float4 a4) {
    return tanh_fast(q4.x + u.x) * a4.x + tanh_fast(q4.y + u.y) * a4.y
         + tanh_fast(q4.z + u.z) * a4.z + tanh_fast(q4.w + u.w) * a4.w;
}

struct SmemGemm { float As[16][68]; float Bs[16][68]; };

// ---- classic combined-load GEMM (used by k_uk; same math as r14) ----
template <bool NT>
__device__ __forceinline__ void gemm64(const float* __restrict__ A, int lda,
                                       const float* __restrict__ B, int ldb,
                                       float* __restrict__ C, int ldc,
                                       const float* __restrict__ bias,
                                       int m0, int n0, int k0, int kiters,
                                       SmemGemm& s)
{
    const int tid = threadIdx.x;
    const int tx = tid & 15, ty = tid >> 4;
    const int am = tid >> 2, ak = (tid & 3) << 2;
    unsigned long long acc2[4][2] = {};

    for (int it = 0; it < kiters; ++it) {
        const int k = k0 + it * 16;
        float4 a4 = *(const float4*)&A[(size_t)(m0 + am) * lda + k + ak];
        float4 b4;
        if (NT) {
            b4 = *(const float4*)&B[(size_t)(n0 + am) * ldb + k + ak];
        } else {
            const int bk = tid >> 4, bn = (tid & 15) << 2;
            b4 = *(const float4*)&B[(size_t)(k + bk) * ldb + n0 + bn];
        }
        __syncthreads();
        s.As[ak + 0][am] = a4.x; s.As[ak + 1][am] = a4.y;
        s.As[ak + 2][am] = a4.z; s.As[ak + 3][am] = a4.w;
        if (NT) {
            s.Bs[ak + 0][am] = b4.x; s.Bs[ak + 1][am] = b4.y;
            s.Bs[ak + 2][am] = b4.z; s.Bs[ak + 3][am] = b4.w;
        } else {
            const int bk = tid >> 4, bn = (tid & 15) << 2;
            *(float4*)&s.Bs[bk][bn] = b4;
        }
        __syncthreads();
        #pragma unroll
        for (int kk = 0; kk < 16; ++kk) {
            float4 av = *(const float4*)&s.As[kk][ty << 2];
            ulonglong2 bp = *(const ulonglong2*)&s.Bs[kk][tx << 2];
            unsigned long long a0 = pack2(av.x), a1 = pack2(av.y);
            unsigned long long a2 = pack2(av.z), a3 = pack2(av.w);
            fma_f32x2(acc2[0][0], a0, bp.x); fma_f32x2(acc2[0][1], a0, bp.y);
            fma_f32x2(acc2[1][0], a1, bp.x); fma_f32x2(acc2[1][1], a1, bp.y);
            fma_f32x2(acc2[2][0], a2, bp.x); fma_f32x2(acc2[2][1], a2, bp.y);
            fma_f32x2(acc2[3][0], a3, bp.x); fma_f32x2(acc2[3][1], a3, bp.y);
        }
    }

    float4 bi = make_float4(0.f, 0.f, 0.f, 0.f);
    if (bias) bi = *(const float4*)&bias[n0 + (tx << 2)];
    #pragma unroll
    for (int u = 0; u < 4; ++u) {
        float2 c01 = unpack2(acc2[u][0]);
        float2 c23 = unpack2(acc2[u][1]);
        float4 o;
        o.x = c01.x + bi.x; o.y = c01.y + bi.y;
        o.z = c23.x + bi.z; o.w = c23.y + bi.w;
        *(float4*)&C[(size_t)(m0 + (ty << 2) + u) * ldc + n0 + (tx << 2)] = o;
    }
}

// ---- PDL-friendly GEMM: B fully preloaded to smem BEFORE griddepsync ----
// preload_B: load all kiters B tiles into Bs[it][16][68].
template <bool NT>
__device__ __forceinline__ void preload_B(const float* __restrict__ B, int ldb,
                                          int n0, int k0, int kiters,
                                          float (*__restrict__ Bs)[16][68],
                                          int tid)
{
    for (int it = 0; it < kiters; ++it) {
        const int k = k0 + it * 16;
        if (NT) {
            const int am = tid >> 2, ak = (tid & 3) << 2;
            float4 b4 = *(const float4*)&B[(size_t)(n0 + am) * ldb + k + ak];
            Bs[it][ak + 0][am] = b4.x; Bs[it][ak + 1][am] = b4.y;
            Bs[it][ak + 2][am] = b4.z; Bs[it][ak + 3][am] = b4.w;
        } else {
            const int bk = tid >> 4, bn = (tid & 15) << 2;
            float4 b4 = *(const float4*)&B[(size_t)(k + bk) * ldb + n0 + bn];
            *(float4*)&Bs[it][bk][bn] = b4;
        }
    }
}

// gemm with preloaded B: post-sync it only streams A and FMAs.
__device__ __forceinline__ void gemm64_preB(const float* __restrict__ A, int lda,
                                            float* __restrict__ C, int ldc,
                                            int m0, int n0, int k0, int kiters,
                                            float (*__restrict__ As)[68],
                                            const float (*__restrict__ Bs)[16][68])
{
    const int tid = threadIdx.x;
    const int tx = tid & 15, ty = tid >> 4;
    const int am = tid >> 2, ak = (tid & 3) << 2;
    unsigned long long acc2[4][2] = {};

    for (int it = 0; it < kiters; ++it) {
        const int k = k0 + it * 16;
        float4 a4 = *(const float4*)&A[(size_t)(m0 + am) * lda + k + ak];
        __syncthreads();                 // also covers Bs preload visibility (it==0)
        As[ak + 0][am] = a4.x; As[ak + 1][am] = a4.y;
        As[ak + 2][am] = a4.z; As[ak + 3][am] = a4.w;
        __syncthreads();
        #pragma unroll
        for (int kk = 0; kk < 16; ++kk) {
            float4 av = *(const float4*)&As[kk][ty << 2];
            ulonglong2 bp = *(const ulonglong2*)&Bs[it][kk][tx << 2];
            unsigned long long a0 = pack2(av.x), a1 = pack2(av.y);
            unsigned long long a2 = pack2(av.z), a3 = pack2(av.w);
            fma_f32x2(acc2[0][0], a0, bp.x); fma_f32x2(acc2[0][1], a0, bp.y);
            fma_f32x2(acc2[1][0], a1, bp.x); fma_f32x2(acc2[1][1], a1, bp.y);
            fma_f32x2(acc2[2][0], a2, bp.x); fma_f32x2(acc2[2][1], a2, bp.y);
            fma_f32x2(acc2[3][0], a3, bp.x); fma_f32x2(acc2[3][1], a3, bp.y);
        }
    }

    #pragma unroll
    for (int u = 0; u < 4; ++u) {
        float2 c01 = unpack2(acc2[u][0]);
        float2 c23 = unpack2(acc2[u][1]);
        float4 o;
        o.x = c01.x; o.y = c01.y; o.z = c23.x; o.w = c23.y;
        *(float4*)&C[(size_t)(m0 + (ty << 2) + u) * ldc + n0 + (tx << 2)] = o;
    }
}

// ---------------- kernels ----------------

__global__ void k_init(const float* __restrict__ e_last,
                       const float* __restrict__ W_ih)
{
    const int i = blockIdx.x * blockDim.x + threadIdx.x;
    const int stride = gridDim.x * blockDim.x;
    if (i < Bn * Dn) g_h[i] = e_last[i];
    if (i < Bn * 16) {                     // zero x + pad region of gin
        int b = i >> 4, k = i & 15;
        g_gin[b * GKP + Dn + k] = 0.f;
    }
    for (int j = i; j < N3 * GKP; j += stride) {
        int n = j / GKP, k = j - n * GKP;
        g_Wpad[j] = (k < GK) ? W_ih[n * GK + k] : 0.f;
    }
}

// Uk = e_all @ Ua_w + Ua_b    (M = B*S = 8192, N = K = 512)
__global__ void k_uk(const float* __restrict__ e_all,
                     const float* __restrict__ Ua_w,
                     const float* __restrict__ Ua_b)
{
    __shared__ SmemGemm s;
    gemm64<false>(e_all, Dn, Ua_w, Dn, g_Uk, Dn, Ua_b,
                  blockIdx.y * 64, blockIdx.x * 64, 0, 32, s);
}

// GRU gates: h(in)+parts -> h(out), PLUS out = h_new @ Wo + b.  grid = 32 CTAs.
__global__ void k_gates(const float* __restrict__ b_ih,
                        const float* __restrict__ b_hh,
                        const float* __restrict__ hin,
                        float* __restrict__ hout,
                        const float* __restrict__ Wo_w,
                        const float* __restrict__ Wo_b,
                        float* __restrict__ d_outputs,
                        int tout)
{
    __shared__ float so[8][3];
    const int tid = threadIdx.x;
    const int lane = tid & 31, wid = tid >> 5;
    const int g = (blockIdx.x * 256 + tid) << 2;  // element base (step 4)
    const int b = g >> 9, j = g & 511;
    const int gb = b * N3 + j;

    // ---- static prologue (overlaps predecessor via PDL) ----
    if (tid < 48) prefetch_L1(&Wo_w[tid * 32]);
    float4 gir = make_float4(b_ih[j], b_ih[j + 1], b_ih[j + 2], b_ih[j + 3]);
    float4 giz = make_float4(b_ih[Dn + j], b_ih[Dn + j + 1],
                             b_ih[Dn + j + 2], b_ih[Dn + j + 3]);
    float4 gnn = make_float4(b_ih[2 * Dn + j], b_ih[2 * Dn + j + 1],
                             b_ih[2 * Dn + j + 2], b_ih[2 * Dn + j + 3]);
    float4 ghr = make_float4(b_hh[j], b_hh[j + 1], b_hh[j + 2], b_hh[j + 3]);
    float4 ghz = make_float4(b_hh[Dn + j], b_hh[Dn + j + 1],
                             b_hh[Dn + j + 2], b_hh[Dn + j + 3]);
    float4 ghn = make_float4(b_hh[2 * Dn + j], b_hh[2 * Dn + j + 1],
                             b_hh[2 * Dn + j + 2], b_hh[2 * Dn + j + 3]);

    cudaGridDependencySynchronize();

    #pragma unroll
    for (int p = 0; p < 4; ++p) {
        add4(gir, &g_gipart[p][gb]);
        add4(giz, &g_gipart[p][gb + Dn]);
        add4(gnn, &g_gipart[p][gb + 2 * Dn]);
        add4(ghr, &g_ghpart[p][gb]);
        add4(ghz, &g_ghpart[p][gb + Dn]);
        add4(ghn, &g_ghpart[p][gb + 2 * Dn]);
    }
    float4 h4 = *(const float4*)&hin[g];
    float4 o;
    o.x = gru_one(gir.x, ghr.x, giz.x, ghz.x, gnn.x, ghn.x, h4.x);
    o.y = gru_one(gir.y, ghr.y, giz.y, ghz.y, gnn.y, ghn.y, h4.y);
    o.z = gru_one(gir.z, ghr.z, giz.z, ghz.z, gnn.z, ghn.z, h4.z);
    o.w = gru_one(gir.w, ghr.w, giz.w, ghz.w, gnn.w, ghn.w, h4.w);
    *(float4*)&hout[g] = o;

    // out[b, c] = sum_j h_new[b,j] * Wo[j,c]
    const float* wp = &Wo_w[j * 3];
    float p0 = o.x * wp[0] + o.y * wp[3] + o.z * wp[6] + o.w * wp[9];
    float p1 = o.x * wp[1] + o.y * wp[4] + o.z * wp[7] + o.w * wp[10];
    float p2 = o.x * wp[2] + o.y * wp[5] + o.z * wp[8] + o.w * wp[11];
    #pragma unroll
    for (int off = 16; off > 0; off >>= 1) {
        p0 += __shfl_down_sync(0xffffffffu, p0, off);
        p1 += __shfl_down_sync(0xffffffffu, p1, off);
        p2 += __shfl_down_sync(0xffffffffu, p2, off);
    }
    if (lane == 0) { so[wid][0] = p0; so[wid][1] = p1; so[wid][2] = p2; }
    __syncthreads();
    if ((tid & 127) < 3) {
        const int c = tid & 127;
        const int w0i = (tid >> 7) << 2;
        const int bb = blockIdx.x * 2 + (tid >> 7);
        float acc = so[w0i][c] + so[w0i + 1][c] + so[w0i + 2][c] + so[w0i + 3][c]
                  + Wo_b[c];
        d_outputs[((size_t)bb * Tn + tout) * 3 + c] = acc;
        g_gin[bb * GKP + Dn + c] = acc;
    }
    cudaTriggerProgrammaticLaunchCompletion();
}

// q partials = h @ Wa  (N=512, split-K 8).  grid = 64 CTAs (8 nt x 8 parts).
// Wa B-tiles fully preloaded to smem BEFORE griddepsync (overlaps k_gates).
__global__ void k_q(const float* __restrict__ Wa_w)
{
    __shared__ __align__(16) float As[16][68];
    __shared__ __align__(16) float Bs[4][16][68];
    const int part = blockIdx.x & 7, nt = blockIdx.x >> 3;
    const int tid = threadIdx.x;

    preload_B<false>(Wa_w, Dn, nt * 64, part * 64, 4, Bs, tid);
    cudaGridDependencySynchronize();

    gemm64_preB(g_h, Dn, g_qpart[part], Dn, 0, nt * 64, part * 64, 4, As, Bs);
    cudaTriggerProgrammaticLaunchCompletion();
}

// fused per-batch attention (r10 internals — fastest measured).  grid = 64.
__global__ void __launch_bounds__(1024, 1)
k_attn(const float* __restrict__ e_all,
       const float* __restrict__ Wa_b,
       const float* __restrict__ Va_w,
       const float* __restrict__ Va_b,
       float* __restrict__ cross, int t)
{
    __shared__ __align__(16) float cpart[8][Dn];   // 16KB, float4-accessed
    __shared__ __align__(16) float qs[Dn];
    __shared__ __align__(16) float vas[Dn];
    __shared__ __align__(16) float ws[Sn];
    __shared__ float red[4];
    __shared__ float smax, sinv;

    const int tid = threadIdx.x;
    const int lane = tid & 31, wid = tid >> 5;
    const int b = blockIdx.x;
    const float* ukb = g_Uk + (size_t)b * Sn * Dn;

    // prologue: warm L1 with this batch's Uk slice (guard t>0: k_uk may be in flight)
    if (t > 0) {
        prefetch_L1(ukb + (size_t)tid * 32);
        prefetch_L1(ukb + (size_t)(tid + 1024) * 32);
    }
    float qb = 0.f, vaw = 0.f;
    if (tid < Dn) { qb = Wa_b[tid]; vaw = Va_w[tid]; }
    const float vb0 = Va_b[0];

    cudaGridDependencySynchronize();

    // q = sum of 8 parts + bias (512 threads), Va -> smem
    if (tid < Dn) {
        float q = qb;
        #pragma unroll
        for (int p = 0; p < 8; ++p) q += g_qpart[p][b * Dn + tid];
        qs[tid] = q;
        vas[tid] = vaw;
    }
    __syncthreads();

    // scores: 32 warps x 4 rows
    #pragma unroll
    for (int r = 0; r < 4; ++r) {
        const int s = (wid << 2) + r;
        const float4* uk4 = (const float4*)(ukb + (size_t)s * Dn);
        float sum = 0.f;
        #pragma unroll
        for (int i = 0; i < 4; ++i) {
            const int v = lane + (i << 5);
            float4 u = uk4[v];
            float4 q4 = *(const float4*)&qs[v << 2];
            float4 a4 = *(const float4*)&vas[v << 2];
            sum += dot_tanh4(q4, u, a4);
        }
        #pragma unroll
        for (int o = 16; o > 0; o >>= 1)
            sum += __shfl_down_sync(0xffffffffu, sum, o);
        if (lane == 0) ws[s] = sum + vb0;
    }
    __syncthreads();

    // softmax over S=128 (first 4 warps)
    float sc = (tid < Sn) ? ws[tid] : -3.4e38f;
    if (tid < Sn) {
        float v = sc;
        #pragma unroll
        for (int o = 16; o > 0; o >>= 1)
            v = fmaxf(v, __shfl_xor_sync(0xffffffffu, v, o));
        if (lane == 0) red[wid] = v;
    }
    __syncthreads();
    if (tid == 0)
        smax = fmaxf(fmaxf(red[0], red[1]), fmaxf(red[2], red[3]));
    __syncthreads();
    float e = 0.f;
    if (tid < Sn) {
        e = __expf(sc - smax);
        float es = e;
        #pragma unroll
        for (int o = 16; o > 0; o >>= 1)
            es += __shfl_xor_sync(0xffffffffu, es, o);
        if (lane == 0) red[wid] = es;
    }
    __syncthreads();
    if (tid == 0)
        sinv = 1.f / (red[0] + red[1] + red[2] + red[3]);
    __syncthreads();
    if (tid < Sn) {
        float w = e * sinv;
        ws[tid] = w;
        cross[((size_t)b * Tn + t) * Sn + tid] = w;
    }
    __syncthreads();

    // ctx: thread handles float4 of d (128 groups), 8 s-groups of 16
    {
        const int d4 = (tid & 127) << 2;
        const int sg = tid >> 7;
        const float4* eb = (const float4*)(e_all + (size_t)b * Sn * Dn + d4);
        float4 a = make_float4(0.f, 0.f, 0.f, 0.f);
        #pragma unroll
        for (int s = sg << 4; s < (sg << 4) + 16; ++s) {
            float4 v = eb[(size_t)s * (Dn / 4)];
            float w = ws[s];
            a.x += w * v.x; a.y += w * v.y; a.z += w * v.z; a.w += w * v.w;
        }
        *(float4*)&cpart[sg][d4] = a;
    }
    __syncthreads();
    if (tid < Dn) {
        float a = 0.f;
        #pragma unroll
        for (int sg = 0; sg < 8; ++sg) a += cpart[sg][tid];
        g_gin[b * GKP + tid] = a;
    }
    cudaTriggerProgrammaticLaunchCompletion();
}

// gi partials (96 CTAs) + gh partials (96 CTAs) in one launch.
// Static B (Wpad / W_hh) fully preloaded to smem BEFORE griddepsync —
// overlaps k_attn's execution; post-sync only A loads + FMAs remain.
__global__ void k_gigh(const float* __restrict__ W_hh)
{
    __shared__ __align__(16) float As[16][68];
    __shared__ __align__(16) float Bs[9][16][68];   // 39168 B (< 48KB static cap)
    const int bx = blockIdx.x;
    const int tid = threadIdx.x;
    if (bx < 96) {
        const int part = bx & 3, nt = bx >> 2;
        const int k0 = (part < 3) ? part * 128 : 384;
        const int ki = (part < 3) ? 8 : 9;
        preload_B<true>(g_Wpad, GKP, nt * 64, k0, ki, Bs, tid);
        cudaGridDependencySynchronize();
        gemm64_preB(g_gin, GKP, g_gipart[part], N3, 0, nt * 64, k0, ki, As, Bs);
    } else {
        const int i = bx - 96;
        const int part = i & 3, nt = i >> 2;
        preload_B<true>(W_hh, Dn, nt * 64, part * 128, 8, Bs, tid);
        cudaGridDependencySynchronize();
        gemm64_preB(g_h, Dn, g_ghpart[part], N3, 0, nt * 64, part * 128, 8, As, Bs);
    }
    cudaTriggerProgrammaticLaunchCompletion();
}

// ---------------- launch helpers ----------------
template <typename F, typename... Args>
static inline void pdl_launch(F* kern, dim3 grid, dim3 block, Args... args)
{
    cudaLaunchConfig_t cfg = {};
    cfg.gridDim = grid;
    cfg.blockDim = block;
    cfg.dynamicSmemBytes = 0;
    cfg.stream = 0;
    cudaLaunchAttribute attr = {};
    attr.id = cudaLaunchAttributeProgrammaticStreamSerialization;
    attr.val.programmaticStreamSerializationAllowed = 1;
    cfg.attrs = &attr;
    cfg.numAttrs = 1;
    cudaLaunchKernelEx(&cfg, kern, args...);
}

// ---------------- launch ----------------
extern "C" void kernel_launch(void* const* d_in, const int* in_sizes, int n_in,
                              void* d_out, int out_size)
{
    const float* e_all  = (const float*)d_in[0];
    const float* e_last = (const float*)d_in[1];
    const float* Wa_w   = (const float*)d_in[2];
    const float* Wa_b   = (const float*)d_in[3];
    const float* Ua_w   = (const float*)d_in[4];
    const float* Ua_b   = (const float*)d_in[5];
    const float* Va_w   = (const float*)d_in[6];
    const float* Va_b   = (const float*)d_in[7];
    const float* W_ih   = (const float*)d_in[8];
    const float* W_hh   = (const float*)d_in[9];
    const float* b_ih   = (const float*)d_in[10];
    const float* b_hh   = (const float*)d_in[11];
    const float* Wo_w   = (const float*)d_in[12];
    const float* Wo_b   = (const float*)d_in[13];

    float* out       = (float*)d_out;
    float* d_outputs = out;                        // [B,T,3]
    float* hT        = out + Bn * Tn * 3;          // [1,B,D]
    float* cross     = hT + Bn * Dn;               // [B,T,S]

    float* g_h_ptr = nullptr;
    cudaGetSymbolAddress((void**)&g_h_ptr, g_h);

    k_init<<<512, 256>>>(e_last, W_ih);
    k_uk<<<dim3(Dn / 64, (Bn * Sn) / 64), 256>>>(e_all, Ua_w, Ua_b);

    for (int t = 0; t < Tn; ++t) {
        if (t > 0)
            pdl_launch(k_gates, dim3(32), dim3(256),
                       b_ih, b_hh, (const float*)g_h_ptr, g_h_ptr,
                       Wo_w, Wo_b, d_outputs, t - 1);
        pdl_launch(k_q, dim3(64), dim3(256), Wa_w);
        pdl_launch(k_attn, dim3(Bn), dim3(1024),
                   e_all, Wa_b, Va_w, Va_b, cross, t);
        pdl_launch(k_gigh, dim3(192), dim3(256), W_hh);
    }
    pdl_launch(k_gates, dim3(32), dim3(256),
               b_ih, b_hh, (const float*)g_h_ptr, hT,
               Wo_w, Wo_b, d_outputs, Tn - 1);
}